// round 12
// baseline (speedup 1.0000x reference)
#include <cuda_runtime.h>
#include <cuda_fp16.h>
#include <cstdint>

// ---------------- problem constants ----------------
static constexpr int MTOT = 8192;   // 4*2048
static constexpr int NTOT = 4096;
static constexpr int KTOT = 4096;

// GEMM tiling (mma.sync path — tcgen05 unavailable: harness targets plain sm_103)
static constexpr int BM = 128;
static constexpr int BN = 256;
static constexpr int BK = 64;                    // 64 halves = 128B fp16 row / 256B fp32 row
static constexpr int NKCHUNK = KTOT / BK;        // 64
static constexpr int STAGES = 2;

static constexpr int A32_BYTES = BM * BK * 4;    // 32768 (fp32 staging)
static constexpr int A16_BYTES = BM * BK * 2;    // 16384 (fp16 ldsm tile)
static constexpr int B_BYTES   = BN * BK * 2;    // 32768
static constexpr int STAGE_BYTES = A32_BYTES + A16_BYTES + B_BYTES;   // 81920
static constexpr int SMEM_TOTAL = STAGES * STAGE_BYTES;               // 163840 (1 CTA/SM)

// ---------------- device scratch (no runtime allocs allowed) ----------------
__device__ double g_partials[1024];
__device__ float  g_scalebuf[2];               // [0]=scale, [1]=scale+EPS
__device__ __half g_Wq[(size_t)NTOT * KTOT];   // 33.5 MB

// ---------------- helpers ----------------
__device__ __forceinline__ unsigned smem_u32(const void* p) {
    unsigned a;
    asm("{ .reg .u64 t; cvta.to.shared.u64 t, %1; cvt.u32.u64 %0, t; }" : "=r"(a) : "l"(p));
    return a;
}
__device__ __forceinline__ void cp_async16(unsigned dst, const void* src) {
    asm volatile("cp.async.cg.shared.global [%0], [%1], 16;" :: "r"(dst), "l"(src) : "memory");
}
__device__ __forceinline__ void cp_commit() { asm volatile("cp.async.commit_group;" ::: "memory"); }

__device__ __forceinline__ void ldsm_x4(unsigned (&r)[4], unsigned addr) {
    asm volatile("ldmatrix.sync.aligned.m8n8.x4.shared.b16 {%0,%1,%2,%3}, [%4];"
                 : "=r"(r[0]), "=r"(r[1]), "=r"(r[2]), "=r"(r[3]) : "r"(addr));
}
__device__ __forceinline__ void mma16816(float (&c)[4], const unsigned (&a)[4],
                                         unsigned b0, unsigned b1) {
    asm volatile("mma.sync.aligned.m16n8k16.row.col.f32.f16.f16.f32 "
                 "{%0,%1,%2,%3}, {%4,%5,%6,%7}, {%8,%9}, {%0,%1,%2,%3};"
                 : "+f"(c[0]), "+f"(c[1]), "+f"(c[2]), "+f"(c[3])
                 : "r"(a[0]), "r"(a[1]), "r"(a[2]), "r"(a[3]), "r"(b0), "r"(b1));
}

// fp16 tile: 128B rows (8 x 16B chunks), chunk swizzled by (row&7) -> ldmatrix conflict-free
__device__ __forceinline__ unsigned tile_off(int row, int chunk) {
    return (unsigned)(row * 128 + ((chunk ^ (row & 7)) << 4));
}

// ---------------- prep kernels ----------------
__global__ void reduce_abs_kernel(const float* __restrict__ W) {
    __shared__ double sh[256];
    double s = 0.0;
    int idx = blockIdx.x * 256 + threadIdx.x;
    #pragma unroll 4
    for (int i = 0; i < 64; ++i) s += (double)fabsf(W[idx + i * 262144]);
    sh[threadIdx.x] = s;
    __syncthreads();
    for (int o = 128; o > 0; o >>= 1) {
        if (threadIdx.x < (unsigned)o) sh[threadIdx.x] += sh[threadIdx.x + o];
        __syncthreads();
    }
    if (threadIdx.x == 0) g_partials[blockIdx.x] = sh[0];
}

__global__ void finalize_scale_kernel() {
    __shared__ double sh[256];
    double s = 0.0;
    for (int i = 0; i < 4; ++i) s += g_partials[threadIdx.x + i * 256];
    sh[threadIdx.x] = s;
    __syncthreads();
    for (int o = 128; o > 0; o >>= 1) {
        if (threadIdx.x < (unsigned)o) sh[threadIdx.x] += sh[threadIdx.x + o];
        __syncthreads();
    }
    if (threadIdx.x == 0) {
        float scale = (float)(sh[0] / 16777216.0);
        g_scalebuf[0] = scale;
        g_scalebuf[1] = scale + 1e-5f;
    }
}

__global__ void quant_w_kernel(const float* __restrict__ W) {
    float denom = g_scalebuf[1];
    int i = blockIdx.x * blockDim.x + threadIdx.x;      // 4 elems each
    float4 w = reinterpret_cast<const float4*>(W)[i];
    // exact IEEE div + rintf (round-half-to-even) matches jnp.round(W/(scale+eps))
    __half2 p0 = __floats2half2_rn(rintf(w.x / denom), rintf(w.y / denom));
    __half2 p1 = __floats2half2_rn(rintf(w.z / denom), rintf(w.w / denom));
    uint2 u;
    u.x = *reinterpret_cast<unsigned*>(&p0);
    u.y = *reinterpret_cast<unsigned*>(&p1);
    reinterpret_cast<uint2*>(g_Wq)[i] = u;
}

// ---------------- GEMM (mma.sync, 512 threads, fused x fp32->fp16 conversion) ----------------
__device__ __forceinline__ void load_stage(unsigned smem_base, int stage, int kc,
                                           int m0, int n0, int tid, const float* x) {
    const unsigned a32 = smem_base + stage * STAGE_BYTES;
    const unsigned b16 = a32 + A32_BYTES + A16_BYTES;
    const int k0 = kc * BK;
    const float* agp = x + (size_t)m0 * KTOT + k0;
    const __half* bgp = g_Wq + (size_t)n0 * KTOT + k0;
    #pragma unroll
    for (int i = 0; i < 4; ++i) {            // A fp32: 128 rows * 16 chunks of 16B = 2048
        int c = tid + i * 512;
        int row = c >> 4, cc = c & 15;
        cp_async16(a32 + row * 256 + cc * 16, agp + (size_t)row * KTOT + cc * 4);
    }
    #pragma unroll
    for (int i = 0; i < 4; ++i) {            // B fp16: 256 rows * 8 chunks of 16B = 2048
        int c = tid + i * 512;
        int row = c >> 3, cc = c & 7;
        cp_async16(b16 + tile_off(row, cc), bgp + (size_t)row * KTOT + cc * 8);
    }
}

__global__ void __launch_bounds__(512, 1) gemm_kernel(float* __restrict__ out,
                                                      const float* __restrict__ x) {
    extern __shared__ char smem[];
    const unsigned smem_base = smem_u32(smem);
    const int tid = threadIdx.x;
    const int wid = tid >> 5;
    const int lane = tid & 31;

    // 16 warps: 4 (m) x 4 (n); warp tile 32x64 -> acc 64 regs/thread
    const int warp_m = wid >> 2;
    const int warp_n = wid & 3;

    // N-fastest rasterization within M-stripes: Wq + x stripe stay L2-resident
    const int m_tile = blockIdx.x >> 4;      // 64 M tiles
    const int n_tile = blockIdx.x & 15;      // 16 N tiles
    const int m0 = m_tile * BM;
    const int n0 = n_tile * BN;

    float acc[2][8][4];                      // 64 regs
    #pragma unroll
    for (int i = 0; i < 2; ++i)
        #pragma unroll
        for (int j = 0; j < 8; ++j)
            #pragma unroll
            for (int q = 0; q < 4; ++q) acc[i][j][q] = 0.f;

    // ldmatrix source offsets (per k-step ks in 0..3, chunk = ks*2 + hi/lo)
    const int a_row_l = (warp_m << 5) + (lane & 15);
    const int a_chk_l = lane >> 4;
    const int b_row_l = (warp_n << 6) + ((lane >> 4) << 3) + (lane & 7);
    const int b_chk_l = (lane >> 3) & 1;

    // prologue: chunk 0 -> stage 0
    load_stage(smem_base, 0, 0, m0, n0, tid, x);
    cp_commit();

    for (int kc = 0; kc < NKCHUNK; ++kc) {
        // stage (kc+1)&1 fully consumed during iter kc-1
        __syncthreads();
        const int kn = kc + 1;
        if (kn < NKCHUNK) load_stage(smem_base, kn & 1, kn, m0, n0, tid, x);
        cp_commit();

        // retire chunk kc's group (kn's stays in flight), publish
        asm volatile("cp.async.wait_group 1;" ::: "memory");
        __syncthreads();

        const unsigned st_off = (unsigned)(kc & 1) * STAGE_BYTES;
        // convert this chunk's A: fp32 staging -> swizzled fp16 tile (2 x 16B chunks/thread)
        {
            const char* a32p = smem + st_off;
            char* a16p = smem + st_off + A32_BYTES;
            #pragma unroll
            for (int i = 0; i < 2; ++i) {
                int c = tid + i * 512;               // 1024 fp16 16B-chunks
                int row = c >> 3, h = c & 7;
                const float4 f0 = *reinterpret_cast<const float4*>(a32p + row * 256 + h * 32);
                const float4 f1 = *reinterpret_cast<const float4*>(a32p + row * 256 + h * 32 + 16);
                __half2 h0 = __floats2half2_rn(f0.x, f0.y);
                __half2 h1 = __floats2half2_rn(f0.z, f0.w);
                __half2 h2 = __floats2half2_rn(f1.x, f1.y);
                __half2 h3 = __floats2half2_rn(f1.z, f1.w);
                uint4 u;
                u.x = *reinterpret_cast<unsigned*>(&h0);
                u.y = *reinterpret_cast<unsigned*>(&h1);
                u.z = *reinterpret_cast<unsigned*>(&h2);
                u.w = *reinterpret_cast<unsigned*>(&h3);
                *reinterpret_cast<uint4*>(a16p + tile_off(row, h)) = u;
            }
        }
        __syncthreads();

        const unsigned a_base = smem_base + st_off + A32_BYTES;
        const unsigned b_base = a_base + A16_BYTES;

        #pragma unroll
        for (int ks = 0; ks < 4; ++ks) {     // four k=16 steps per BK=64 chunk
            unsigned afr[2][4];
            #pragma unroll
            for (int im = 0; im < 2; ++im)
                ldsm_x4(afr[im], a_base + tile_off(a_row_l + im * 16, ks * 2 + a_chk_l));
            unsigned bfr[4][4];
            #pragma unroll
            for (int in2 = 0; in2 < 4; ++in2)
                ldsm_x4(bfr[in2], b_base + tile_off(b_row_l + in2 * 16, ks * 2 + b_chk_l));
            #pragma unroll
            for (int im = 0; im < 2; ++im)
                #pragma unroll
                for (int inn = 0; inn < 8; ++inn)
                    mma16816(acc[im][inn], afr[im],
                             bfr[inn >> 1][(inn & 1) * 2], bfr[inn >> 1][(inn & 1) * 2 + 1]);
        }
    }

    // epilogue: scale + store fp32
    const float scale = g_scalebuf[0];
    const int grp = lane >> 2;
    const int tig = lane & 3;
    #pragma unroll
    for (int im = 0; im < 2; ++im) {
        const int r0 = m0 + warp_m * 32 + im * 16 + grp;
        #pragma unroll
        for (int inn = 0; inn < 8; ++inn) {
            const int cidx = n0 + warp_n * 64 + inn * 8 + tig * 2;
            float2 v0, v1;
            v0.x = acc[im][inn][0] * scale;  v0.y = acc[im][inn][1] * scale;
            v1.x = acc[im][inn][2] * scale;  v1.y = acc[im][inn][3] * scale;
            *reinterpret_cast<float2*>(out + (size_t)r0 * NTOT + cidx) = v0;
            *reinterpret_cast<float2*>(out + (size_t)(r0 + 8) * NTOT + cidx) = v1;
        }
    }
}

// ---------------- launcher ----------------
extern "C" void kernel_launch(void* const* d_in, const int* in_sizes, int n_in,
                              void* d_out, int out_size) {
    const float* x = (const float*)d_in[0];
    const float* W = (const float*)d_in[1];
    // robustness: identify by element count (x: 33.5M, W: 16.7M)
    if (n_in >= 2 && in_sizes[0] == NTOT * KTOT && in_sizes[1] == MTOT * KTOT) {
        x = (const float*)d_in[1];
        W = (const float*)d_in[0];
    }

    cudaFuncSetAttribute(gemm_kernel, cudaFuncAttributeMaxDynamicSharedMemorySize, SMEM_TOTAL);

    reduce_abs_kernel<<<1024, 256>>>(W);
    finalize_scale_kernel<<<1, 256>>>();
    quant_w_kernel<<<16384, 256>>>(W);
    gemm_kernel<<<(MTOT / BM) * (NTOT / BN), 512, SMEM_TOTAL>>>((float*)d_out, x);
}

// round 13
// speedup vs baseline: 1.2949x; 1.2949x over previous
#include <cuda_runtime.h>
#include <cuda_fp16.h>
#include <cstdint>

// ---------------- problem constants ----------------
static constexpr int MTOT = 8192;   // 4*2048
static constexpr int NTOT = 4096;
static constexpr int KTOT = 4096;

// GEMM tiling (mma.sync path — tcgen05 unavailable: harness targets plain sm_103)
// R8 config: proven 742.4us. smem + tensor co-bound; fusion/restructure falsified.
static constexpr int BM = 128;
static constexpr int BN = 256;
static constexpr int BK = 64;                    // 64 halves = 128B per smem row
static constexpr int NKCHUNK = KTOT / BK;        // 64
static constexpr int STAGES = 4;

static constexpr int A_BYTES = BM * BK * 2;      // 16384
static constexpr int B_BYTES = BN * BK * 2;      // 32768
static constexpr int STAGE_BYTES = A_BYTES + B_BYTES;          // 49152
static constexpr int SMEM_TOTAL = STAGES * STAGE_BYTES;        // 196608 (1 CTA/SM)

// ---------------- device scratch (no runtime allocs allowed) ----------------
__device__ double g_partials[1024];
__device__ float  g_scalebuf[2];               // [0]=scale, [1]=scale+EPS
__device__ __half g_Wq[(size_t)NTOT * KTOT];   // 33.5 MB
__device__ __half g_xh[(size_t)MTOT * KTOT];   // 67 MB

// ---------------- helpers ----------------
__device__ __forceinline__ unsigned smem_u32(const void* p) {
    unsigned a;
    asm("{ .reg .u64 t; cvta.to.shared.u64 t, %1; cvt.u32.u64 %0, t; }" : "=r"(a) : "l"(p));
    return a;
}
__device__ __forceinline__ void cp_async16(unsigned dst, const void* src) {
    asm volatile("cp.async.cg.shared.global [%0], [%1], 16;" :: "r"(dst), "l"(src) : "memory");
}
__device__ __forceinline__ void cp_commit() { asm volatile("cp.async.commit_group;" ::: "memory"); }

__device__ __forceinline__ void ldsm_x4(unsigned (&r)[4], unsigned addr) {
    asm volatile("ldmatrix.sync.aligned.m8n8.x4.shared.b16 {%0,%1,%2,%3}, [%4];"
                 : "=r"(r[0]), "=r"(r[1]), "=r"(r[2]), "=r"(r[3]) : "r"(addr));
}
__device__ __forceinline__ void mma16816(float (&c)[4], const unsigned (&a)[4],
                                         unsigned b0, unsigned b1) {
    asm volatile("mma.sync.aligned.m16n8k16.row.col.f32.f16.f16.f32 "
                 "{%0,%1,%2,%3}, {%4,%5,%6,%7}, {%8,%9}, {%0,%1,%2,%3};"
                 : "+f"(c[0]), "+f"(c[1]), "+f"(c[2]), "+f"(c[3])
                 : "r"(a[0]), "r"(a[1]), "r"(a[2]), "r"(a[3]), "r"(b0), "r"(b1));
}

// smem tile layout: 128B rows (8 x 16B chunks), chunk swizzled by (row&7) -> ldmatrix conflict-free
__device__ __forceinline__ unsigned tile_off(int row, int chunk) {
    return (unsigned)(row * 128 + ((chunk ^ (row & 7)) << 4));
}

// ---------------- prep kernels ----------------
__global__ void reduce_abs_kernel(const float* __restrict__ W) {
    // float4 loads: 16 iters x 16B per thread, block-contiguous 16KB slabs
    __shared__ double sh[256];
    double s = 0.0;
    const float4* Wv = reinterpret_cast<const float4*>(W);
    int idx = blockIdx.x * 256 + threadIdx.x;           // float4 index
    #pragma unroll 4
    for (int i = 0; i < 16; ++i) {
        float4 v = Wv[idx + i * 262144];
        s += (double)fabsf(v.x) + (double)fabsf(v.y)
           + (double)fabsf(v.z) + (double)fabsf(v.w);
    }
    sh[threadIdx.x] = s;
    __syncthreads();
    for (int o = 128; o > 0; o >>= 1) {
        if (threadIdx.x < (unsigned)o) sh[threadIdx.x] += sh[threadIdx.x + o];
        __syncthreads();
    }
    if (threadIdx.x == 0) g_partials[blockIdx.x] = sh[0];
}

__global__ void finalize_scale_kernel() {
    __shared__ double sh[256];
    double s = 0.0;
    for (int i = 0; i < 4; ++i) s += g_partials[threadIdx.x + i * 256];
    sh[threadIdx.x] = s;
    __syncthreads();
    for (int o = 128; o > 0; o >>= 1) {
        if (threadIdx.x < (unsigned)o) sh[threadIdx.x] += sh[threadIdx.x + o];
        __syncthreads();
    }
    if (threadIdx.x == 0) {
        float scale = (float)(sh[0] / 16777216.0);
        g_scalebuf[0] = scale;
        g_scalebuf[1] = scale + 1e-5f;
    }
}

__global__ void quant_w_kernel(const float* __restrict__ W) {
    float denom = g_scalebuf[1];
    int i = blockIdx.x * blockDim.x + threadIdx.x;      // 4 elems each
    float4 w = reinterpret_cast<const float4*>(W)[i];
    // exact IEEE div + rintf (round-half-to-even) matches jnp.round(W/(scale+eps))
    __half2 p0 = __floats2half2_rn(rintf(w.x / denom), rintf(w.y / denom));
    __half2 p1 = __floats2half2_rn(rintf(w.z / denom), rintf(w.w / denom));
    uint2 u;
    u.x = *reinterpret_cast<unsigned*>(&p0);
    u.y = *reinterpret_cast<unsigned*>(&p1);
    reinterpret_cast<uint2*>(g_Wq)[i] = u;
}

__global__ void convert_x_kernel(const float* __restrict__ x) {
    size_t i = (size_t)blockIdx.x * blockDim.x + threadIdx.x;
    const float4* xin = reinterpret_cast<const float4*>(x);
    float4 v0 = xin[i * 2];
    float4 v1 = xin[i * 2 + 1];
    __half2 a0 = __floats2half2_rn(v0.x, v0.y);
    __half2 a1 = __floats2half2_rn(v0.z, v0.w);
    __half2 a2 = __floats2half2_rn(v1.x, v1.y);
    __half2 a3 = __floats2half2_rn(v1.z, v1.w);
    uint4 u;
    u.x = *reinterpret_cast<unsigned*>(&a0);
    u.y = *reinterpret_cast<unsigned*>(&a1);
    u.z = *reinterpret_cast<unsigned*>(&a2);
    u.w = *reinterpret_cast<unsigned*>(&a3);
    reinterpret_cast<uint4*>(g_xh)[i] = u;
}

// ---------------- GEMM (mma.sync, 512 threads, 4-stage — R8 proven config) ----------------
__device__ __forceinline__ void load_stage(unsigned smem_base, int stage, int kc,
                                           int m0, int n0, int tid) {
    const unsigned a_base = smem_base + stage * STAGE_BYTES;
    const unsigned b_base = a_base + A_BYTES;
    const int k0 = kc * BK;
    const __half* agp = g_xh + (size_t)m0 * KTOT + k0;
    const __half* bgp = g_Wq + (size_t)n0 * KTOT + k0;
    #pragma unroll
    for (int i = 0; i < 2; ++i) {            // A: 128 rows * 8 chunks = 1024
        int c = tid + i * 512;
        int row = c >> 3, cc = c & 7;
        cp_async16(a_base + tile_off(row, cc), agp + (size_t)row * KTOT + cc * 8);
    }
    #pragma unroll
    for (int i = 0; i < 4; ++i) {            // B: 256 rows * 8 chunks = 2048
        int c = tid + i * 512;
        int row = c >> 3, cc = c & 7;
        cp_async16(b_base + tile_off(row, cc), bgp + (size_t)row * KTOT + cc * 8);
    }
}

__global__ void __launch_bounds__(512, 1) gemm_kernel(float* __restrict__ out) {
    extern __shared__ char smem[];
    const unsigned smem_base = smem_u32(smem);
    const int tid = threadIdx.x;
    const int wid = tid >> 5;
    const int lane = tid & 31;

    // 16 warps: 4 (m) x 4 (n); warp tile 32x64 -> acc 64 regs/thread
    const int warp_m = wid >> 2;
    const int warp_n = wid & 3;

    // N-fastest rasterization within M-stripes: Wq stays L2-resident
    const int m_tile = blockIdx.x >> 4;      // 64 M tiles
    const int n_tile = blockIdx.x & 15;      // 16 N tiles
    const int m0 = m_tile * BM;
    const int n0 = n_tile * BN;

    float acc[2][8][4];                      // 64 regs
    #pragma unroll
    for (int i = 0; i < 2; ++i)
        #pragma unroll
        for (int j = 0; j < 8; ++j)
            #pragma unroll
            for (int q = 0; q < 4; ++q) acc[i][j][q] = 0.f;

    // ldmatrix source offsets (per k-step ks in 0..3, chunk = ks*2 + hi/lo)
    const int a_row_l = (warp_m << 5) + (lane & 15);
    const int a_chk_l = lane >> 4;
    const int b_row_l = (warp_n << 6) + ((lane >> 4) << 3) + (lane & 7);
    const int b_chk_l = (lane >> 3) & 1;

    // prologue: fill STAGES-1 = 3 stages
    #pragma unroll
    for (int s = 0; s < STAGES - 1; ++s) {
        load_stage(smem_base, s, s, m0, n0, tid);
        cp_commit();
    }

    for (int kc = 0; kc < NKCHUNK; ++kc) {
        asm volatile("cp.async.wait_group 2;" ::: "memory");
        __syncthreads();

        // prefetch chunk kc+3 into stage (kc+3)&3 (held chunk kc-1, consumed; safe after sync)
        const int kn = kc + STAGES - 1;
        if (kn < NKCHUNK) load_stage(smem_base, kn & 3, kn, m0, n0, tid);
        cp_commit();

        const unsigned a_base = smem_base + (kc & 3) * STAGE_BYTES;
        const unsigned b_base = a_base + A_BYTES;

        #pragma unroll
        for (int ks = 0; ks < 4; ++ks) {     // four k=16 steps per BK=64 chunk
            unsigned afr[2][4];
            #pragma unroll
            for (int im = 0; im < 2; ++im)
                ldsm_x4(afr[im], a_base + tile_off(a_row_l + im * 16, ks * 2 + a_chk_l));
            unsigned bfr[4][4];
            #pragma unroll
            for (int in2 = 0; in2 < 4; ++in2)
                ldsm_x4(bfr[in2], b_base + tile_off(b_row_l + in2 * 16, ks * 2 + b_chk_l));
            #pragma unroll
            for (int im = 0; im < 2; ++im)
                #pragma unroll
                for (int inn = 0; inn < 8; ++inn)
                    mma16816(acc[im][inn], afr[im],
                             bfr[inn >> 1][(inn & 1) * 2], bfr[inn >> 1][(inn & 1) * 2 + 1]);
        }
    }

    // epilogue: scale + store fp32
    const float scale = g_scalebuf[0];
    const int grp = lane >> 2;
    const int tig = lane & 3;
    #pragma unroll
    for (int im = 0; im < 2; ++im) {
        const int r0 = m0 + warp_m * 32 + im * 16 + grp;
        #pragma unroll
        for (int inn = 0; inn < 8; ++inn) {
            const int cidx = n0 + warp_n * 64 + inn * 8 + tig * 2;
            float2 v0, v1;
            v0.x = acc[im][inn][0] * scale;  v0.y = acc[im][inn][1] * scale;
            v1.x = acc[im][inn][2] * scale;  v1.y = acc[im][inn][3] * scale;
            *reinterpret_cast<float2*>(out + (size_t)r0 * NTOT + cidx) = v0;
            *reinterpret_cast<float2*>(out + (size_t)(r0 + 8) * NTOT + cidx) = v1;
        }
    }
}

// ---------------- launcher ----------------
extern "C" void kernel_launch(void* const* d_in, const int* in_sizes, int n_in,
                              void* d_out, int out_size) {
    const float* x = (const float*)d_in[0];
    const float* W = (const float*)d_in[1];
    // robustness: identify by element count (x: 33.5M, W: 16.7M)
    if (n_in >= 2 && in_sizes[0] == NTOT * KTOT && in_sizes[1] == MTOT * KTOT) {
        x = (const float*)d_in[1];
        W = (const float*)d_in[0];
    }

    cudaFuncSetAttribute(gemm_kernel, cudaFuncAttributeMaxDynamicSharedMemorySize, SMEM_TOTAL);

    reduce_abs_kernel<<<1024, 256>>>(W);
    finalize_scale_kernel<<<1, 256>>>();
    quant_w_kernel<<<16384, 256>>>(W);
    convert_x_kernel<<<16384, 256>>>(x);
    gemm_kernel<<<(MTOT / BM) * (NTOT / BN), 512, SMEM_TOTAL>>>((float*)d_out);
}